// round 15
// baseline (speedup 1.0000x reference)
#include <cuda_runtime.h>
#include <cuda_bf16.h>
#include <cstdint>

// Problem constants (shape fixed by dataset: img [64, 3, 512, 512])
constexpr int NCH = 192;           // 64*3 channels
constexpr int P   = 262144;        // 512*512 pixels / channel
constexpr int NB  = 256;           // bins

// Pipeline structure (R7/R13 topology)
constexpr int GROUPS = 8;
constexpr int CPG    = NCH / GROUPS;   // 24 channels per group
constexpr int HPC    = 8;              // hist blocks per channel
constexpr int APC    = 16;             // apply blocks per channel
constexpr int NHIST  = CPG * HPC;      // 192
constexpr int NAPPLY = CPG * APC;      // 384
constexpr int NBLK   = NHIST + NAPPLY; // 576 <= 148*4 -> fully co-resident
constexpr int WINDOW = 2;              // hist may run at most 2 groups ahead

// Scratch — __device__ globals.
// g_part: per-slice partial histograms, plain stores, overwritten every run.
// g_ctr:  hist-done per group (release apply).
// g_fin:  apply-done per group (backpressure hist).
__device__ int g_part[NCH * HPC * NB];   // 1.57 MB
__device__ int g_ctr [GROUPS];
__device__ int g_fin [GROUPS];

// ---------------------------------------------------------------------------
// Fused persistent kernel with producer throttling:
//  - 192 hist blocks (read-bound): before group g (g>=2) wait until apply has
//    fully finished group g-2, keeping <=~50MB of input in flight -> apply's
//    re-reads stay L2-resident. Then stream input, plain-store partials,
//    bump g_ctr[g].
//  - 384 apply blocks (write-bound): spin on g_ctr[g], build LUT locally from
//    the 8 partials (exact PIL math), translate + __stcs-write slice, bump
//    g_fin[g].
// DRAM traffic target: 201MB input (once) + 201MB output = 402MB.
// ---------------------------------------------------------------------------
__global__ void __launch_bounds__(256, 4) fused_kernel(const float* __restrict__ in,
                                                       float* __restrict__ out) {
    __shared__ int sh[8 * NB];     // hist: 8 per-warp hists. apply: H/CS/RED/LUT.
    const int tid = threadIdx.x;
    const int bid = blockIdx.x;

    if (bid < NHIST) {
        // ---------------- HIST ROLE (R13 + backpressure wait) ----------------
        const int cg = bid / HPC;          // channel within group
        const int h  = bid % HPC;          // slice within channel
        int* const myh = &sh[(tid >> 5) * NB];

        for (int g = 0; g < GROUPS; g++) {
            // Backpressure: don't run more than WINDOW groups ahead of apply.
            if (g >= WINDOW) {
                if (tid == 0) {
                    while (*(volatile int*)&g_fin[g - WINDOW] < NAPPLY)
                        __nanosleep(128);
                }
                __syncthreads();
            }

            const int c = g * CPG + cg;
            for (int i = tid; i < 8 * NB; i += 256) sh[i] = 0;
            __syncthreads();

            const float4* bi =
                reinterpret_cast<const float4*>(in + (size_t)c * P) + h * (P / 4 / HPC);
            for (int i = tid; i < P / 4 / HPC; i += 512) {   // 8192 float4 / slice
                float4 a = bi[i];
                float4 b = bi[i + 256];
                atomicAdd(&myh[(int)a.x], 1);
                atomicAdd(&myh[(int)a.y], 1);
                atomicAdd(&myh[(int)a.z], 1);
                atomicAdd(&myh[(int)a.w], 1);
                atomicAdd(&myh[(int)b.x], 1);
                atomicAdd(&myh[(int)b.y], 1);
                atomicAdd(&myh[(int)b.z], 1);
                atomicAdd(&myh[(int)b.w], 1);
            }
            __syncthreads();

            // Reduce 8 warp-hists -> plain store of this slice's partial.
            int s = 0;
#pragma unroll
            for (int k = 0; k < 8; k++) s += sh[k * NB + tid];
            g_part[(c * HPC + h) * NB + tid] = s;

            __threadfence();               // release my partial before counting
            __syncthreads();               // all threads' stores+fences done
            if (tid == 0) atomicAdd(&g_ctr[g], 1);
        }
    } else {
        // ---------------- APPLY ROLE (R13 + completion bump) ----------------
        const int a  = bid - NHIST;
        const int cg = a / APC;            // channel within group
        const int j  = a % APC;            // slice within channel
        int*   H   = sh;
        int*   CS  = sh + NB;
        int*   RED = sh + 2 * NB;
        float* LUT = reinterpret_cast<float*>(sh + 3 * NB);

        for (int g = 0; g < GROUPS; g++) {
            const int c = g * CPG + cg;

            // Wait until all hist blocks of this group have published.
            if (tid == 0) {
                while (*(volatile int*)&g_ctr[g] < NHIST) __nanosleep(128);
            }
            __syncthreads();
            __threadfence();

            // Build this channel's LUT locally (exact PIL integer math).
            int hv = 0;
#pragma unroll
            for (int k = 0; k < HPC; k++)
                hv += __ldcg(&g_part[(c * HPC + k) * NB + tid]);
            H[tid]  = hv;
            CS[tid] = hv;
            __syncthreads();
#pragma unroll
            for (int off = 1; off < NB; off <<= 1) {       // inclusive scan
                int v = (tid >= off) ? CS[tid - off] : 0;
                __syncthreads();
                CS[tid] += v;
                __syncthreads();
            }
            RED[tid] = hv ? tid : -1;                      // last nonzero bin
            __syncthreads();
#pragma unroll
            for (int sdx = 128; sdx > 0; sdx >>= 1) {
                if (tid < sdx) RED[tid] = max(RED[tid], RED[tid + sdx]);
                __syncthreads();
            }
            const int last_val = H[RED[0]];
            const int step = (P - last_val) / 255;
            const int safe = step > 0 ? step : 1;
            const int prev = tid ? CS[tid - 1] : 0;
            int lv = (prev + step / 2) / safe;
            lv = min(max(lv, 0), 255);
            if (step == 0) lv = tid;       // passthrough as identity LUT
            LUT[tid] = (float)lv;
            __syncthreads();

            // Apply this block's slice: 4096 float4, 2 loads in flight.
            // Input reads should now be L2 hits (window-bounded residency).
            const float4* bi =
                reinterpret_cast<const float4*>(in + (size_t)c * P) + j * (P / 4 / APC);
            float4* bo =
                reinterpret_cast<float4*>(out + (size_t)c * P) + j * (P / 4 / APC);
            for (int i = tid; i < P / 4 / APC; i += 512) {
                float4 x = bi[i];
                float4 y = bi[i + 256];
                float4 ox, oy;
                ox.x = LUT[(int)x.x]; ox.y = LUT[(int)x.y];
                ox.z = LUT[(int)x.z]; ox.w = LUT[(int)x.w];
                oy.x = LUT[(int)y.x]; oy.y = LUT[(int)y.y];
                oy.z = LUT[(int)y.z]; oy.w = LUT[(int)y.w];
                __stcs(&bo[i], ox);            // streaming: don't evict input
                __stcs(&bo[i + 256], oy);
            }
            __syncthreads();                    // smem reuse next group

            // Report this block done with group g (feeds hist backpressure).
            if (tid == 0) atomicAdd(&g_fin[g], 1);
        }
    }
}

// ---------------------------------------------------------------------------
// Tiny cleanup: reset the 16 group counters for the next graph replay.
// ---------------------------------------------------------------------------
__global__ void cleanup_kernel() {
    if (threadIdx.x < GROUPS) {
        g_ctr[threadIdx.x] = 0;
        g_fin[threadIdx.x] = 0;
    }
}

// ---------------------------------------------------------------------------
extern "C" void kernel_launch(void* const* d_in, const int* in_sizes, int n_in,
                              void* d_out, int out_size) {
    const float* img = (const float*)d_in[0];
    float* out = (float*)d_out;

    fused_kernel<<<NBLK, 256>>>(img, out);
    cleanup_kernel<<<1, 32>>>();
}